// round 6
// baseline (speedup 1.0000x reference)
#include <cuda_runtime.h>

#define PI_F 3.14159265358979323846f
typedef unsigned long long ull;

// ---------------- constant tables computed on-device from the small inputs ----
// pk[72]: packed coefficient per f32x2 product, lane order fixed by the product
//         schedule below. .x = packed (A_lo, A_hi), .y = packed (B_lo, B_hi).
struct Params {
    ulonglong2 pk[72];
    float  K[9];        // e = sum K[3r+s] * (1,C1,S1)_r * (1,C2,S2)_s
    float  W0, W1, b0, b1;
};
__device__ Params g_params;

// compile-time 16th-root twiddle table: W16[k] = (cos, sin)(2*pi*k/16)
__constant__ float2 W16[16] = {
    { 1.0000000000f,  0.0000000000f}, { 0.9238795325f,  0.3826834324f},
    { 0.7071067812f,  0.7071067812f}, { 0.3826834324f,  0.9238795325f},
    { 0.0000000000f,  1.0000000000f}, {-0.3826834324f,  0.9238795325f},
    {-0.7071067812f,  0.7071067812f}, {-0.9238795325f,  0.3826834324f},
    {-1.0000000000f,  0.0000000000f}, {-0.9238795325f, -0.3826834324f},
    {-0.7071067812f, -0.7071067812f}, {-0.3826834324f, -0.9238795325f},
    { 0.0000000000f, -1.0000000000f}, { 0.3826834324f, -0.9238795325f},
    { 0.7071067812f, -0.7071067812f}, { 0.9238795325f, -0.3826834324f}};

__device__ __forceinline__ float2 cmulf(float2 a, float2 b) {
    return make_float2(a.x * b.x - a.y * b.y, a.x * b.y + a.y * b.x);
}
__device__ __forceinline__ ull packull(float lo, float hi) {
    return (ull)__float_as_uint(lo) | ((ull)__float_as_uint(hi) << 32);
}

// ---------------- setup: build U1 (16x16), U2 (4x4), fold into pk/K ---------
__global__ void setup_kernel(const float* __restrict__ f1, const float* __restrict__ p1,
                             const float* __restrict__ f2, const float* __restrict__ p2,
                             const float* __restrict__ W, const float* __restrict__ bb) {
    __shared__ float2 U[256];
    __shared__ float2 V[256];
    __shared__ float  At[256];
    __shared__ float  Bt[256];
    __shared__ float2 U2s[16];
    __shared__ float2 V2s[16];

    const int t = threadIdx.x;
    const int r = t >> 4, c = t & 15;
    const float p1_0 = p1[0], p1_1 = p1[1];
    float sn_p11, cs_p11; sincosf(0.5f * p1_1, &sn_p11, &cs_p11);

    // ---- U1: init = (fused RZ diag) * QFT ----
    {
        float ph = 0.0f;
        ph += (((r >> 3) & 1) ? 0.5f : -0.5f) * f1[0];
        ph += (((r >> 2) & 1) ? 0.5f : -0.5f) * f1[1];
        ph += (((r >> 1) & 1) ? 0.5f : -0.5f) * f1[2];
        ph += (((r     ) & 1) ? 0.5f : -0.5f) * f1[3];
        float sp, cp; sincosf(ph, &sp, &cp);
        float2 w = W16[(r * c) & 15];
        U[t] = make_float2(0.25f * (w.x * cp - w.y * sp),
                           0.25f * (w.y * cp + w.x * sp));
    }
    __syncthreads();
    // Qdag @ U  (the only dense matmul)
    {
        float2 acc = make_float2(0.f, 0.f);
        #pragma unroll
        for (int k = 0; k < 16; ++k) {
            float2 w = W16[(r * k) & 15];      // conj(w) = (w.x, -w.y)
            float2 u = U[k * 16 + c];
            acc.x += w.x * u.x + w.y * u.y;
            acc.y += w.x * u.y - w.y * u.x;
        }
        V[t] = make_float2(0.25f * acc.x, 0.25f * acc.y);
    }
    __syncthreads();
    U[t] = V[t];
    __syncthreads();

    // g1: CRZ(p1_0) ctrl bit3, tgt bit2
    if ((r >> 3) & 1) {
        float ang = (((r >> 2) & 1) ? 0.5f : -0.5f) * p1_0;
        float sn, cs; sincosf(ang, &sn, &cs);
        U[t] = cmulf(U[t], make_float2(cs, sn));
    }
    __syncthreads();
    // g2: X mask 8
    V[t] = U[((r ^ 8) << 4) | c]; __syncthreads(); U[t] = V[t]; __syncthreads();
    // g3: CRX(p1_1) ctrl bit3, tgt mask 4
    {
        float2 u = U[t];
        if ((r >> 3) & 1) {
            float2 v = U[((r ^ 4) << 4) | c];
            u = make_float2(cs_p11 * u.x + sn_p11 * v.y, cs_p11 * u.y - sn_p11 * v.x);
        }
        V[t] = u;
    }
    __syncthreads(); U[t] = V[t]; __syncthreads();
    // g4: X mask 8
    V[t] = U[((r ^ 8) << 4) | c]; __syncthreads(); U[t] = V[t]; __syncthreads();
    // g5: CRZ(p1_0) ctrl bit1, tgt bit0
    if ((r >> 1) & 1) {
        float ang = ((r & 1) ? 0.5f : -0.5f) * p1_0;
        float sn, cs; sincosf(ang, &sn, &cs);
        U[t] = cmulf(U[t], make_float2(cs, sn));
    }
    __syncthreads();
    // g6: X mask 2
    V[t] = U[((r ^ 2) << 4) | c]; __syncthreads(); U[t] = V[t]; __syncthreads();
    // g7: CRX(p1_1) ctrl bit1, tgt mask 1
    {
        float2 u = U[t];
        if ((r >> 1) & 1) {
            float2 v = U[((r ^ 1) << 4) | c];
            u = make_float2(cs_p11 * u.x + sn_p11 * v.y, cs_p11 * u.y - sn_p11 * v.x);
        }
        V[t] = u;
    }
    __syncthreads(); U[t] = V[t]; __syncthreads();
    // g8: X mask 2
    V[t] = U[((r ^ 2) << 4) | c]; __syncthreads(); U[t] = V[t]; __syncthreads();

    // ---- full tables: A = Re(U1^H Z1 U1), B = Re(U1^H Z3 U1) (no doubling) --
    {
        const int i = r, j = c;
        float av = 0.f, bv = 0.f;
        #pragma unroll
        for (int m = 0; m < 16; ++m) {
            float2 ui = U[m * 16 + i], uj = U[m * 16 + j];
            float re = ui.x * uj.x + ui.y * uj.y;     // Re(conj(ui)*uj)
            float z1 = 1.f - 2.f * (float)((m >> 2) & 1);
            float z3 = 1.f - 2.f * (float)(m & 1);
            av += z1 * re;
            bv += z3 * re;
        }
        At[t] = av;
        Bt[t] = bv;
    }
    __syncthreads();

    // ---- pack coefficients in the exact product-lane order of the main loop -
    if (t == 0) {
        auto ca = [&](int i, int j) { return (i == j) ? At[i * 16 + j] : 2.f * At[i * 16 + j]; };
        auto cb = [&](int i, int j) { return (i == j) ? Bt[i * 16 + j] : 2.f * Bt[i * 16 + j]; };
        int p = 0;
        // P: v_k * v_m  -> lanes (2k,2m), (2k+1,2m+1)
        for (int k = 0; k < 8; ++k)
            for (int m = k; m < 8; ++m) {
                ulonglong2 e;
                e.x = packull(ca(2 * k, 2 * m), ca(2 * k + 1, 2 * m + 1));
                e.y = packull(cb(2 * k, 2 * m), cb(2 * k + 1, 2 * m + 1));
                g_params.pk[p++] = e;
            }
        // Q: v_k * swap(v_m), k<m -> lanes (2k,2m+1), (2k+1,2m)
        for (int k = 0; k < 8; ++k)
            for (int m = k + 1; m < 8; ++m) {
                ulonglong2 e;
                e.x = packull(ca(2 * k, 2 * m + 1), ca(2 * k + 1, 2 * m));
                e.y = packull(cb(2 * k, 2 * m + 1), cb(2 * k + 1, 2 * m));
                g_params.pk[p++] = e;
            }
        // R: v_k * swap(v_k) -> lane lo = (2k,2k+1), hi duplicate -> coeff 0
        for (int k = 0; k < 8; ++k) {
            ulonglong2 e;
            e.x = packull(ca(2 * k, 2 * k + 1), 0.f);
            e.y = packull(cb(2 * k, 2 * k + 1), 0.f);
            g_params.pk[p++] = e;
        }
    }

    // ---- U2 (4x4) ----
    if (t < 16) {
        int r2 = t >> 2, c2 = t & 3;
        float ph = ((((r2 >> 1) & 1) ? 0.5f : -0.5f) * f2[0])
                 + ((( r2       & 1) ? 0.5f : -0.5f) * f2[1]);
        float sp, cp; sincosf(ph, &sp, &cp);
        float2 w = W16[((r2 * c2) & 3) * 4];
        U2s[t] = make_float2(0.5f * (w.x * cp - w.y * sp),
                             0.5f * (w.y * cp + w.x * sp));
    }
    __syncthreads();
    if (t < 16) {  // Q2dag @ U2
        int r2 = t >> 2, c2 = t & 3;
        float2 acc = make_float2(0.f, 0.f);
        #pragma unroll
        for (int k = 0; k < 4; ++k) {
            float2 w = W16[((r2 * k) & 3) * 4];
            float2 u = U2s[k * 4 + c2];
            acc.x += w.x * u.x + w.y * u.y;
            acc.y += w.x * u.y - w.y * u.x;
        }
        V2s[t] = make_float2(0.5f * acc.x, 0.5f * acc.y);
    }
    __syncthreads();
    if (t < 16) {  // CRZ(p2[0]) ctrl bit1, tgt bit0
        int r2 = t >> 2;
        float2 u = V2s[t];
        if ((r2 >> 1) & 1) {
            float ang = ((r2 & 1) ? 0.5f : -0.5f) * p2[0];
            float sn, cs; sincosf(ang, &sn, &cs);
            u = cmulf(u, make_float2(cs, sn));
        }
        U2s[t] = u;
    }
    __syncthreads();
    if (t < 16) {  // X mask 2
        int r2 = t >> 2, c2 = t & 3;
        V2s[t] = U2s[((r2 ^ 2) << 2) | c2];
    }
    __syncthreads();
    if (t < 16) {  // CRX(p2[1]) ctrl bit1, tgt mask 1
        int r2 = t >> 2, c2 = t & 3;
        float2 u = V2s[t];
        if ((r2 >> 1) & 1) {
            float sn, cs; sincosf(0.5f * p2[1], &sn, &cs);
            float2 v = V2s[((r2 ^ 1) << 2) | c2];
            u = make_float2(cs * u.x + sn * v.y, cs * u.y - sn * v.x);
        }
        U2s[t] = u;
    }
    __syncthreads();
    if (t < 16) {  // X mask 2 (final U2 ends in V2s)
        int r2 = t >> 2, c2 = t & 3;
        V2s[t] = U2s[((r2 ^ 2) << 2) | c2];
    }
    __syncthreads();

    // ---- fold layer-2 into K ----
    if (t == 0) {
        float C[4][4];
        #pragma unroll
        for (int i = 0; i < 4; ++i)
            #pragma unroll
            for (int j = 0; j < 4; ++j) {
                float acc = 0.f;
                #pragma unroll
                for (int m = 0; m < 4; ++m) {
                    float2 ui = V2s[m * 4 + i], uj = V2s[m * 4 + j];
                    float z = 1.f - 2.f * (float)(m & 1);
                    acc += z * (ui.x * uj.x + ui.y * uj.y);
                }
                C[i][j] = acc;
            }
        float T[3][3];
        T[0][0] = C[0][0];            T[0][1] = 2.f * C[0][1];                   T[0][2] = C[1][1];
        T[1][0] = 2.f * C[0][2];      T[1][1] = 2.f * C[0][3] + 2.f * C[1][2];   T[1][2] = 2.f * C[1][3];
        T[2][0] = C[2][2];            T[2][1] = 2.f * C[2][3];                   T[2][2] = C[3][3];
        const float G[3][3] = {{0.5f, 0.5f, 0.f}, {0.f, 0.f, 0.5f}, {0.5f, -0.5f, 0.f}};
        #pragma unroll
        for (int rr = 0; rr < 3; ++rr)
            #pragma unroll
            for (int ss = 0; ss < 3; ++ss) {
                float k = 0.f;
                #pragma unroll
                for (int a = 0; a < 3; ++a)
                    #pragma unroll
                    for (int b2 = 0; b2 < 3; ++b2)
                        k += G[a][rr] * T[a][b2] * G[b2][ss];
                g_params.K[rr * 3 + ss] = k;
            }
        g_params.W0 = W[0];  g_params.W1 = W[1];
        g_params.b0 = bb[0]; g_params.b1 = bb[1];
    }
}

// ---------------- packed f32x2 helpers ----------------
__device__ __forceinline__ ull fma2(ull a, ull b, ull c) {
    ull d;
    asm("fma.rn.f32x2 %0, %1, %2, %3;" : "=l"(d) : "l"(a), "l"(b), "l"(c));
    return d;
}
__device__ __forceinline__ ull swap2(ull v) {
    unsigned int lo, hi;
    asm("mov.b64 {%0, %1}, %2;" : "=r"(lo), "=r"(hi) : "l"(v));
    ull d;
    asm("mov.b64 %0, {%1, %2};" : "=l"(d) : "r"(hi), "r"(lo));
    return d;
}
__device__ __forceinline__ void upk2(ull v, float& lo, float& hi) {
    unsigned int a, b;
    asm("mov.b64 {%0, %1}, %2;" : "=r"(a), "=r"(b) : "l"(v));
    lo = __uint_as_float(a); hi = __uint_as_float(b);
}

// ---------------- main kernel: 2 batch elements per thread, FFMA2 core -------
__global__ __launch_bounds__(256) void qfcn_main(const float* __restrict__ x,
                                                 float2* __restrict__ out, int half) {
    __shared__ ulonglong2 spk[72];
    __shared__ float cK[13];
    {
        int t = threadIdx.x;
        if (t < 72) spk[t] = g_params.pk[t];
        if (t >= 72 && t < 85) cK[t - 72] = (&g_params.K[0])[t - 72];
    }
    __syncthreads();

    int gid = blockIdx.x * 256 + threadIdx.x;
    if (gid >= half) return;

    // 16 floats per element = 4 ulonglong2; pairs (x2k, x2k+1) fall out aligned
    const ulonglong2* pa = (const ulonglong2*)x + (size_t)gid * 4;
    const ulonglong2* pb = (const ulonglong2*)x + ((size_t)gid + (size_t)half) * 4;

    ull vA[8], vB[8];
    #pragma unroll
    for (int q = 0; q < 4; ++q) {
        ulonglong2 u = pa[q];
        vA[2 * q] = u.x; vA[2 * q + 1] = u.y;
        ulonglong2 w = pb[q];
        vB[2 * q] = w.x; vB[2 * q + 1] = w.y;
    }
    ull sA[8], sB[8];
    #pragma unroll
    for (int k = 0; k < 8; ++k) { sA[k] = swap2(vA[k]); sB[k] = swap2(vB[k]); }

    const ull Z = 0ull;
    const ull ONE2 = 0x3F8000003F800000ull;   // (1.0f, 1.0f)
    ull e1A = Z, e3A = Z, ssA = Z;
    ull e1B = Z, e3B = Z, ssB = Z;

    int p = 0;
    // P: v_k * v_m (includes diagonal squares feeding ss)
    #pragma unroll
    for (int k = 0; k < 8; ++k) {
        #pragma unroll
        for (int m = k; m < 8; ++m) {
            ull prA = fma2(vA[k], vA[m], Z);
            ull prB = fma2(vB[k], vB[m], Z);
            ulonglong2 cc = spk[p];
            e1A = fma2(prA, cc.x, e1A);  e3A = fma2(prA, cc.y, e3A);
            e1B = fma2(prB, cc.x, e1B);  e3B = fma2(prB, cc.y, e3B);
            if (m == k) { ssA = fma2(prA, ONE2, ssA); ssB = fma2(prB, ONE2, ssB); }
            ++p;
        }
    }
    // Q: v_k * swap(v_m), k<m
    #pragma unroll
    for (int k = 0; k < 8; ++k) {
        #pragma unroll
        for (int m = k + 1; m < 8; ++m) {
            ull prA = fma2(vA[k], sA[m], Z);
            ull prB = fma2(vB[k], sB[m], Z);
            ulonglong2 cc = spk[p];
            e1A = fma2(prA, cc.x, e1A);  e3A = fma2(prA, cc.y, e3A);
            e1B = fma2(prB, cc.x, e1B);  e3B = fma2(prB, cc.y, e3B);
            ++p;
        }
    }
    // R: v_k * swap(v_k) -> lo lane = x_{2k} x_{2k+1} (hi coeff = 0)
    #pragma unroll
    for (int k = 0; k < 8; ++k) {
        ull prA = fma2(vA[k], sA[k], Z);
        ull prB = fma2(vB[k], sB[k], Z);
        ulonglong2 cc = spk[p];
        e1A = fma2(prA, cc.x, e1A);  e3A = fma2(prA, cc.y, e3A);
        e1B = fma2(prB, cc.x, e1B);  e3B = fma2(prB, cc.y, e3B);
        ++p;
    }

    float e1al, e1ah, e3al, e3ah, sal, sah;
    float e1bl, e1bh, e3bl, e3bh, sbl, sbh;
    upk2(e1A, e1al, e1ah); upk2(e3A, e3al, e3ah); upk2(ssA, sal, sah);
    upk2(e1B, e1bl, e1bh); upk2(e3B, e3bl, e3bh); upk2(ssB, sbl, sbh);
    float e1a = e1al + e1ah, e3a = e3al + e3ah, ssa = sal + sah;
    float e1b = e1bl + e1bh, e3b = e3bl + e3bh, ssb = sbl + sbh;

    const float K0 = cK[0], K1 = cK[1], K2 = cK[2];
    const float K3 = cK[3], K4 = cK[4], K5 = cK[5];
    const float K6 = cK[6], K7 = cK[7], K8 = cK[8];
    const float W0 = cK[9], W1 = cK[10], b0 = cK[11], b1 = cK[12];

    auto head = [&](float q1, float q3, float s) -> float2 {
        float inv = __fdividef(1.0f, s);
        float t1 = q1 * inv, t3 = q3 * inv;          // <Z_1>, <Z_3> in [-1,1]
        float s1, c1, s2, c2;
        __sincosf(t1, &s1, &c1);
        __sincosf(t3, &s2, &c2);
        float e = K0 + K1 * c2 + K2 * s2
                + c1 * (K3 + K4 * c2 + K5 * s2)
                + s1 * (K6 + K7 * c2 + K8 * s2);
        return make_float2(fmaf(e, W0, b0), fmaf(e, W1, b1));
    };

    out[gid]        = head(e1a, e3a, ssa);
    out[gid + half] = head(e1b, e3b, ssb);
}

extern "C" void kernel_launch(void* const* d_in, const int* in_sizes, int n_in,
                              void* d_out, int out_size) {
    const float* x  = (const float*)d_in[0];
    const float* f1 = (const float*)d_in[1];
    const float* p1 = (const float*)d_in[2];
    const float* f2 = (const float*)d_in[3];
    const float* p2 = (const float*)d_in[4];
    const float* W  = (const float*)d_in[5];
    const float* b  = (const float*)d_in[6];

    int B = in_sizes[0] / 16;
    int half = B >> 1;

    setup_kernel<<<1, 256>>>(f1, p1, f2, p2, W, b);
    int blocks = (half + 255) / 256;
    qfcn_main<<<blocks, 256>>>(x, (float2*)d_out, half);
}

// round 10
// speedup vs baseline: 1.0165x; 1.0165x over previous
#include <cuda_runtime.h>

#define PI_F 3.14159265358979323846f

// ---------------- constant tables computed on-device from the small inputs ----
struct Params {
    float2 pair[136];   // (i<=j) upper-tri order: {a, b}, off-diag pre-doubled
    float  K[9];        // e = sum K[3r+s] * (1,C1,S1)_r * (1,C2,S2)_s
    float  W0, W1, b0, b1;
};
__device__ Params g_params;

// compile-time 16th-root twiddle table: W16[k] = (cos, sin)(2*pi*k/16)
__constant__ float2 W16[16] = {
    { 1.0000000000f,  0.0000000000f}, { 0.9238795325f,  0.3826834324f},
    { 0.7071067812f,  0.7071067812f}, { 0.3826834324f,  0.9238795325f},
    { 0.0000000000f,  1.0000000000f}, {-0.3826834324f,  0.9238795325f},
    {-0.7071067812f,  0.7071067812f}, {-0.9238795325f,  0.3826834324f},
    {-1.0000000000f,  0.0000000000f}, {-0.9238795325f, -0.3826834324f},
    {-0.7071067812f, -0.7071067812f}, {-0.3826834324f, -0.9238795325f},
    { 0.0000000000f, -1.0000000000f}, { 0.3826834324f, -0.9238795325f},
    { 0.7071067812f, -0.7071067812f}, { 0.9238795325f, -0.3826834324f}};

__device__ __forceinline__ float2 cmulf(float2 a, float2 b) {
    return make_float2(a.x * b.x - a.y * b.y, a.x * b.y + a.y * b.x);
}

// ---------------- setup: build U1 (16x16), U2 (4x4), fold into A/B/K ---------
__global__ void setup_kernel(const float* __restrict__ f1, const float* __restrict__ p1,
                             const float* __restrict__ f2, const float* __restrict__ p2,
                             const float* __restrict__ W, const float* __restrict__ bb) {
    __shared__ float2 U[256];
    __shared__ float2 V[256];
    __shared__ float2 U2s[16];
    __shared__ float2 V2s[16];

    const int t = threadIdx.x;
    const int r = t >> 4, c = t & 15;
    const float p1_0 = p1[0], p1_1 = p1[1];
    float sn_p11, cs_p11; sincosf(0.5f * p1_1, &sn_p11, &cs_p11);

    // ---- U1: init = (fused RZ diag) * QFT ----
    {
        float ph = 0.0f;
        ph += (((r >> 3) & 1) ? 0.5f : -0.5f) * f1[0];
        ph += (((r >> 2) & 1) ? 0.5f : -0.5f) * f1[1];
        ph += (((r >> 1) & 1) ? 0.5f : -0.5f) * f1[2];
        ph += (((r     ) & 1) ? 0.5f : -0.5f) * f1[3];
        float sp, cp; sincosf(ph, &sp, &cp);
        float2 w = W16[(r * c) & 15];
        U[t] = make_float2(0.25f * (w.x * cp - w.y * sp),
                           0.25f * (w.y * cp + w.x * sp));
    }
    __syncthreads();
    // Qdag @ U  (the only dense matmul) — twiddle conj from the constant table
    {
        float2 acc = make_float2(0.f, 0.f);
        #pragma unroll
        for (int k = 0; k < 16; ++k) {
            float2 w = W16[(r * k) & 15];      // conj(w) = (w.x, -w.y)
            float2 u = U[k * 16 + c];
            acc.x += w.x * u.x + w.y * u.y;
            acc.y += w.x * u.y - w.y * u.x;
        }
        V[t] = make_float2(0.25f * acc.x, 0.25f * acc.y);
    }
    __syncthreads();
    U[t] = V[t];
    __syncthreads();

    // g1: CRZ(p1_0) ctrl bit3, tgt bit2 (diag in-place)
    if ((r >> 3) & 1) {
        float ang = (((r >> 2) & 1) ? 0.5f : -0.5f) * p1_0;
        float sn, cs; sincosf(ang, &sn, &cs);
        U[t] = cmulf(U[t], make_float2(cs, sn));
    }
    __syncthreads();
    // g2: X mask 8
    V[t] = U[((r ^ 8) << 4) | c]; __syncthreads(); U[t] = V[t]; __syncthreads();
    // g3: CRX(p1_1) ctrl bit3, tgt mask 4
    {
        float2 u = U[t];
        if ((r >> 3) & 1) {
            float2 v = U[((r ^ 4) << 4) | c];
            u = make_float2(cs_p11 * u.x + sn_p11 * v.y, cs_p11 * u.y - sn_p11 * v.x);
        }
        V[t] = u;
    }
    __syncthreads(); U[t] = V[t]; __syncthreads();
    // g4: X mask 8
    V[t] = U[((r ^ 8) << 4) | c]; __syncthreads(); U[t] = V[t]; __syncthreads();
    // g5: CRZ(p1_0) ctrl bit1, tgt bit0
    if ((r >> 1) & 1) {
        float ang = ((r & 1) ? 0.5f : -0.5f) * p1_0;
        float sn, cs; sincosf(ang, &sn, &cs);
        U[t] = cmulf(U[t], make_float2(cs, sn));
    }
    __syncthreads();
    // g6: X mask 2
    V[t] = U[((r ^ 2) << 4) | c]; __syncthreads(); U[t] = V[t]; __syncthreads();
    // g7: CRX(p1_1) ctrl bit1, tgt mask 1
    {
        float2 u = U[t];
        if ((r >> 1) & 1) {
            float2 v = U[((r ^ 1) << 4) | c];
            u = make_float2(cs_p11 * u.x + sn_p11 * v.y, cs_p11 * u.y - sn_p11 * v.x);
        }
        V[t] = u;
    }
    __syncthreads(); U[t] = V[t]; __syncthreads();
    // g8: X mask 2
    V[t] = U[((r ^ 2) << 4) | c]; __syncthreads(); U[t] = V[t]; __syncthreads();

    // ---- pair table: A = Re(U1^H Z1 U1), B = Re(U1^H Z3 U1) ----
    if (r <= c) {
        const int i = r, j = c;
        float av = 0.f, bv = 0.f;
        #pragma unroll
        for (int m = 0; m < 16; ++m) {
            float2 ui = U[m * 16 + i], uj = U[m * 16 + j];
            float re = ui.x * uj.x + ui.y * uj.y;     // Re(conj(ui)*uj)
            float z1 = 1.f - 2.f * (float)((m >> 2) & 1);
            float z3 = 1.f - 2.f * (float)(m & 1);
            av += z1 * re;
            bv += z3 * re;
        }
        float w = (i < j) ? 2.f : 1.f;
        int idx = i * 16 - (i * (i - 1)) / 2 + (j - i);
        g_params.pair[idx] = make_float2(w * av, w * bv);
    }

    // ---- U2 (4x4) ----
    if (t < 16) {
        int r2 = t >> 2, c2 = t & 3;
        float ph = ((((r2 >> 1) & 1) ? 0.5f : -0.5f) * f2[0])
                 + ((( r2       & 1) ? 0.5f : -0.5f) * f2[1]);
        float sp, cp; sincosf(ph, &sp, &cp);
        float2 w = W16[((r2 * c2) & 3) * 4];
        U2s[t] = make_float2(0.5f * (w.x * cp - w.y * sp),
                             0.5f * (w.y * cp + w.x * sp));
    }
    __syncthreads();
    if (t < 16) {  // Q2dag @ U2
        int r2 = t >> 2, c2 = t & 3;
        float2 acc = make_float2(0.f, 0.f);
        #pragma unroll
        for (int k = 0; k < 4; ++k) {
            float2 w = W16[((r2 * k) & 3) * 4];   // use conj(w)
            float2 u = U2s[k * 4 + c2];
            acc.x += w.x * u.x + w.y * u.y;
            acc.y += w.x * u.y - w.y * u.x;
        }
        V2s[t] = make_float2(0.5f * acc.x, 0.5f * acc.y);
    }
    __syncthreads();
    if (t < 16) {  // CRZ(p2[0]) ctrl bit1, tgt bit0
        int r2 = t >> 2;
        float2 u = V2s[t];
        if ((r2 >> 1) & 1) {
            float ang = ((r2 & 1) ? 0.5f : -0.5f) * p2[0];
            float sn, cs; sincosf(ang, &sn, &cs);
            u = cmulf(u, make_float2(cs, sn));
        }
        U2s[t] = u;
    }
    __syncthreads();
    if (t < 16) {  // X mask 2
        int r2 = t >> 2, c2 = t & 3;
        V2s[t] = U2s[((r2 ^ 2) << 2) | c2];
    }
    __syncthreads();
    if (t < 16) {  // CRX(p2[1]) ctrl bit1, tgt mask 1
        int r2 = t >> 2, c2 = t & 3;
        float2 u = V2s[t];
        if ((r2 >> 1) & 1) {
            float sn, cs; sincosf(0.5f * p2[1], &sn, &cs);
            float2 v = V2s[((r2 ^ 1) << 2) | c2];
            u = make_float2(cs * u.x + sn * v.y, cs * u.y - sn * v.x);
        }
        U2s[t] = u;
    }
    __syncthreads();
    if (t < 16) {  // X mask 2 (final U2 ends in V2s)
        int r2 = t >> 2, c2 = t & 3;
        V2s[t] = U2s[((r2 ^ 2) << 2) | c2];
    }
    __syncthreads();

    // ---- fold layer-2 into K ----
    if (t == 0) {
        float C[4][4];
        #pragma unroll
        for (int i = 0; i < 4; ++i)
            #pragma unroll
            for (int j = 0; j < 4; ++j) {
                float acc = 0.f;
                #pragma unroll
                for (int m = 0; m < 4; ++m) {
                    float2 ui = V2s[m * 4 + i], uj = V2s[m * 4 + j];
                    float z = 1.f - 2.f * (float)(m & 1);
                    acc += z * (ui.x * uj.x + ui.y * uj.y);
                }
                C[i][j] = acc;
            }
        float T[3][3];
        T[0][0] = C[0][0];            T[0][1] = 2.f * C[0][1];                   T[0][2] = C[1][1];
        T[1][0] = 2.f * C[0][2];      T[1][1] = 2.f * C[0][3] + 2.f * C[1][2];   T[1][2] = 2.f * C[1][3];
        T[2][0] = C[2][2];            T[2][1] = 2.f * C[2][3];                   T[2][2] = C[3][3];
        const float G[3][3] = {{0.5f, 0.5f, 0.f}, {0.f, 0.f, 0.5f}, {0.5f, -0.5f, 0.f}};
        #pragma unroll
        for (int rr = 0; rr < 3; ++rr)
            #pragma unroll
            for (int ss = 0; ss < 3; ++ss) {
                float k = 0.f;
                #pragma unroll
                for (int a = 0; a < 3; ++a)
                    #pragma unroll
                    for (int b2 = 0; b2 < 3; ++b2)
                        k += G[a][rr] * T[a][b2] * G[b2][ss];
                g_params.K[rr * 3 + ss] = k;
            }
        g_params.W0 = W[0];  g_params.W1 = W[1];
        g_params.b0 = bb[0]; g_params.b1 = bb[1];
    }
}

// ---------------- main kernel: 1 batch element per thread, pure scalar FFMA --
__global__ __launch_bounds__(256) void qfcn_main(const float* __restrict__ x,
                                                 float2* __restrict__ out, int n) {
    __shared__ float2 cpair[136];
    __shared__ float  cK[13];
    {
        int t = threadIdx.x;
        if (t < 136) cpair[t] = g_params.pair[t];
        if (t >= 136 && t < 149) cK[t - 136] = (&g_params.K[0])[t - 136];
    }
    __syncthreads();

    int gid = blockIdx.x * 256 + threadIdx.x;
    if (gid >= n) return;

    const float4* px = (const float4*)x + (size_t)gid * 4;
    float xv[16];
    #pragma unroll
    for (int q = 0; q < 4; ++q) {
        float4 u = px[q];
        xv[q * 4 + 0] = u.x; xv[q * 4 + 1] = u.y; xv[q * 4 + 2] = u.z; xv[q * 4 + 3] = u.w;
    }

    // 2-way split accumulators for ILP
    float e10 = 0.f, e11 = 0.f, e30 = 0.f, e31 = 0.f, ss0 = 0.f, ss1 = 0.f;

    int idx = 0;
    #pragma unroll
    for (int i = 0; i < 16; ++i) {
        #pragma unroll
        for (int j = i; j < 16; ++j) {
            float2 cc = cpair[idx];
            float ta = xv[i] * xv[j];
            if (idx & 1) {
                e10 = fmaf(ta, cc.x, e10);  e30 = fmaf(ta, cc.y, e30);
            } else {
                e11 = fmaf(ta, cc.x, e11);  e31 = fmaf(ta, cc.y, e31);
            }
            if (j == i) { if (i & 1) ss0 += ta; else ss1 += ta; }
            ++idx;
        }
    }
    float e1 = e10 + e11, e3 = e30 + e31, ss = ss0 + ss1;

    const float K0 = cK[0], K1 = cK[1], K2 = cK[2];
    const float K3 = cK[3], K4 = cK[4], K5 = cK[5];
    const float K6 = cK[6], K7 = cK[7], K8 = cK[8];
    const float W0 = cK[9], W1 = cK[10], b0 = cK[11], b1 = cK[12];

    float inv = __fdividef(1.0f, ss);
    float t1 = e1 * inv, t3 = e3 * inv;          // <Z_1>, <Z_3>  in [-1,1]
    float s1, c1, s2, c2;
    __sincosf(t1, &s1, &c1);
    __sincosf(t3, &s2, &c2);
    float e = K0 + K1 * c2 + K2 * s2
            + c1 * (K3 + K4 * c2 + K5 * s2)
            + s1 * (K6 + K7 * c2 + K8 * s2);
    out[gid] = make_float2(fmaf(e, W0, b0), fmaf(e, W1, b1));
}

extern "C" void kernel_launch(void* const* d_in, const int* in_sizes, int n_in,
                              void* d_out, int out_size) {
    const float* x  = (const float*)d_in[0];
    const float* f1 = (const float*)d_in[1];
    const float* p1 = (const float*)d_in[2];
    const float* f2 = (const float*)d_in[3];
    const float* p2 = (const float*)d_in[4];
    const float* W  = (const float*)d_in[5];
    const float* b  = (const float*)d_in[6];

    int B = in_sizes[0] / 16;

    setup_kernel<<<1, 256>>>(f1, p1, f2, p2, W, b);
    int blocks = (B + 255) / 256;
    qfcn_main<<<blocks, 256>>>(x, (float2*)d_out, B);
}